// round 16
// baseline (speedup 1.0000x reference)
#include <cuda_runtime.h>
#include <cuda_fp16.h>
#include <cstdint>

#define IN_DIM  256
#define OUT_DIM 128
#define B_ROWS  4096
#define N_COLS  8192
#define ALPHA   0.2f
#define NSPLIT  8
#define NCHUNK  (N_COLS / NSPLIT)  // 1024 n per split
#define KT      32                 // n per K-tile
#define NT      (NCHUNK / KT)      // 32 tiles
#define ATILE   8192               // A tile bytes: 128 rows x 64B
#define BTILE   8192               // B tile bytes: 32 rows x 256B

// ---------------- device scratch (static, allocation-free) ----------------
__device__ __align__(16) __half g_hb[N_COLS * OUT_DIM];          // 2 MB, swizzled
// w tiles: [btile 32][split 8][ktile 32][8192 B] = 64 MB, smem-image layout
__device__ __align__(16) char g_wt[(size_t)32 * NSPLIT * NT * ATILE];
__device__ float g_s2[N_COLS];
__device__ float g_p[N_COLS];
__device__ float g_q[N_COLS];
__device__ float g_t[B_ROWS];   // -s1[b]
__device__ float g_P[B_ROWS];
__device__ float g_Q[B_ROWS];
// static-init; replays recompute the same max (atomicMax idempotent at max)
__device__ unsigned int g_s2max_bits = 0u;
__device__ __align__(16) float g_part[(size_t)NSPLIT * B_ROWS * OUT_DIM]; // 16 MB

// ---------------- helpers ----------------
__device__ __forceinline__ uint32_t smem_u32(const void* p) {
    uint32_t a;
    asm("{ .reg .u64 t; cvta.to.shared.u64 t, %1; cvt.u32.u64 %0, t; }"
        : "=r"(a) : "l"(p));
    return a;
}
__device__ __forceinline__ void cpa16(uint32_t s, const void* g) {
    asm volatile("cp.async.cg.shared.global [%0], [%1], 16;" :: "r"(s), "l"(g));
}
__device__ __forceinline__ void cp_bulk(uint32_t dst, const void* src,
                                        uint32_t bytes, uint32_t mbar) {
    asm volatile(
        "cp.async.bulk.shared::cta.global.mbarrier::complete_tx::bytes "
        "[%0], [%1], %2, [%3];"
        :: "r"(dst), "l"(src), "r"(bytes), "r"(mbar) : "memory");
}
__device__ __forceinline__ void ldsm4(uint32_t* r, uint32_t a) {
    asm volatile("ldmatrix.sync.aligned.m8n8.x4.shared.b16 {%0,%1,%2,%3}, [%4];"
                 : "=r"(r[0]), "=r"(r[1]), "=r"(r[2]), "=r"(r[3]) : "r"(a));
}
__device__ __forceinline__ void ldsm4t(uint32_t* r, uint32_t a) {
    asm volatile("ldmatrix.sync.aligned.m8n8.x4.trans.shared.b16 {%0,%1,%2,%3}, [%4];"
                 : "=r"(r[0]), "=r"(r[1]), "=r"(r[2]), "=r"(r[3]) : "r"(a));
}
__device__ __forceinline__ void mma_f16(float* d, const uint32_t* a,
                                        uint32_t b0, uint32_t b1) {
    asm volatile(
        "mma.sync.aligned.m16n8k16.row.col.f32.f16.f16.f32 "
        "{%0,%1,%2,%3},{%4,%5,%6,%7},{%8,%9},{%0,%1,%2,%3};"
        : "+f"(d[0]), "+f"(d[1]), "+f"(d[2]), "+f"(d[3])
        : "r"(a[0]), "r"(a[1]), "r"(a[2]), "r"(a[3]), "r"(b0), "r"(b1));
}
#define MBAR_INIT(mb, c) \
    asm volatile("mbarrier.init.shared.b64 [%0], %1;" :: "r"((uint32_t)(mb)), "r"((uint32_t)(c)) : "memory")
#define MBAR_EXPECT(mb, bytes) \
    asm volatile("mbarrier.arrive.expect_tx.shared.b64 _, [%0], %1;" \
                 :: "r"((uint32_t)(mb)), "r"((uint32_t)(bytes)) : "memory")
#define MBAR_WAIT(mb, ph) do {                                                   \
    uint32_t _m = (uint32_t)(mb), _p = (uint32_t)(ph), _d;                       \
    asm volatile("{\n\t.reg .pred p;\n\t"                                        \
        "mbarrier.try_wait.parity.acquire.cta.shared::cta.b64 p, [%1], %2;\n\t"  \
        "selp.b32 %0, 1, 0, p;\n\t}" : "=r"(_d) : "r"(_m), "r"(_p) : "memory");  \
    if (!_d) {                                                                   \
        asm volatile("{\n\t.reg .pred P1;\n\t"                                   \
            "WL_%=:\n\t"                                                         \
            "mbarrier.try_wait.parity.acquire.cta.shared::cta.b64 P1, [%0], %1, 0x989680;\n\t" \
            "@P1 bra.uni WD_%=;\n\t"                                             \
            "bra.uni WL_%=;\n\t"                                                 \
            "WD_%=:\n\t}" :: "r"(_m), "r"(_p) : "memory");                       \
    }                                                                            \
} while (0)
__device__ __forceinline__ unsigned int f2key(float f) {
    int i = __float_as_int(f);
    return (i >= 0) ? ((unsigned)i ^ 0x80000000u) : ~(unsigned)i;
}
__device__ __forceinline__ float key2f(unsigned int k) {
    int i = (k & 0x80000000u) ? (int)(k ^ 0x80000000u) : (int)~k;
    return __int_as_float(i);
}

// ---------------- K1: k_prep — Wa1 (local), s1 -> g_t ----------------
__global__ __launch_bounds__(256) void k_prep(const float* __restrict__ gf,
                                              const int* __restrict__ nodes,
                                              const float* __restrict__ W,
                                              const float* __restrict__ a1) {
    __shared__ float sWa1[IN_DIM];
    int t = threadIdx.x, lane = t & 31, wid = t >> 5;
    {
        const float* row = W + t * OUT_DIM;
        float s = 0.f;
#pragma unroll 8
        for (int c = 0; c < OUT_DIM; c++) s += row[c] * a1[c];
        sWa1[t] = s;
    }
    __syncthreads();
#pragma unroll
    for (int rr = 0; rr < 4; rr++) {
        int b = blockIdx.x * 32 + wid * 4 + rr;
        const float* row = gf + (size_t)nodes[b] * IN_DIM;
        float s = 0.f;
#pragma unroll
        for (int k = lane; k < IN_DIM; k += 32) s += row[k] * sWa1[k];
#pragma unroll
        for (int o = 16; o; o >>= 1) s += __shfl_xor_sync(0xffffffffu, s, o);
        if (lane == 0) g_t[b] = -s;
    }
}

// ---------------- K2: k_hneigh — pipelined h = gf[un]@W; s2, max ----------
// h stored swizzled: row r, 16B chunk c placed at c ^ (r & 7).
__global__ __launch_bounds__(256) void k_hneigh(
    const float* __restrict__ gf, const int* __restrict__ un,
    const float* __restrict__ W, const float* __restrict__ a2) {
    __shared__ __align__(16) float As[2][32][36];
    __shared__ __align__(16) float Ws[2][32][132];
    int t = threadIdx.x, lane = t & 31, wid = t >> 5;
    int r0 = blockIdx.x * 32;

    const int arow = t >> 3, ach = t & 7;
    const float* asrc = gf + (size_t)un[r0 + arow] * IN_DIM + ach * 4;
    uint32_t adst[2] = {smem_u32(&As[0][arow][ach * 4]),
                        smem_u32(&As[1][arow][ach * 4])};
    uint32_t wdst[2][4];
    const float* wsrc[4];
#pragma unroll
    for (int u = 0; u < 4; u++) {
        int idx = t * 4 + u, wrow = idx >> 5, wch = idx & 31;
        wsrc[u] = W + (size_t)wrow * OUT_DIM + wch * 4;
        wdst[0][u] = smem_u32(&Ws[0][wrow][wch * 4]);
        wdst[1][u] = smem_u32(&Ws[1][wrow][wch * 4]);
    }

    cpa16(adst[0], asrc);
#pragma unroll
    for (int u = 0; u < 4; u++) cpa16(wdst[0][u], wsrc[u]);
    asm volatile("cp.async.commit_group;");

    float acc[4][4] = {};
    for (int kb = 0; kb < 8; kb++) {
        const int cur = kb & 1;
        if (kb + 1 < 8) {
            cpa16(adst[cur ^ 1], asrc + (kb + 1) * 32);
#pragma unroll
            for (int u = 0; u < 4; u++)
                cpa16(wdst[cur ^ 1][u], wsrc[u] + (size_t)(kb + 1) * 32 * OUT_DIM);
            asm volatile("cp.async.commit_group;");
            asm volatile("cp.async.wait_group 1;");
        } else {
            asm volatile("cp.async.wait_group 0;");
        }
        __syncthreads();
#pragma unroll
        for (int kk = 0; kk < 32; kk++) {
            float4 wv = *(const float4*)&Ws[cur][kk][4 * lane];
            float wvv[4] = {wv.x, wv.y, wv.z, wv.w};
            float av[4];
#pragma unroll
            for (int i = 0; i < 4; i++) av[i] = As[cur][wid + 8 * i][kk];
#pragma unroll
            for (int i = 0; i < 4; i++)
#pragma unroll
                for (int c = 0; c < 4; c++) acc[i][c] += av[i] * wvv[c];
        }
        __syncthreads();
    }

    float4 a2v = *(const float4*)&a2[4 * lane];
    float wmax = -1e30f;
    char* hb = (char*)g_hb;
#pragma unroll
    for (int i = 0; i < 4; i++) {
        int r = r0 + wid + 8 * i;
        float part = acc[i][0] * a2v.x + acc[i][1] * a2v.y +
                     acc[i][2] * a2v.z + acc[i][3] * a2v.w;
#pragma unroll
        for (int o = 16; o; o >>= 1) part += __shfl_xor_sync(0xffffffffu, part, o);
        if (lane == 0) {
            g_s2[r] = part;
            wmax = fmaxf(wmax, part);
        }
        __half2 h01 = __floats2half2_rn(acc[i][0], acc[i][1]);
        __half2 h23 = __floats2half2_rn(acc[i][2], acc[i][3]);
        uint32_t off = (uint32_t)r * 256 + (((lane >> 1) ^ (r & 7)) << 4) +
                       (lane & 1) * 8;
        *(uint2*)(hb + off) = make_uint2(*(uint32_t*)&h01, *(uint32_t*)&h23);
    }
    if (lane == 0) atomicMax(&g_s2max_bits, f2key(wmax));
}

// ---------------- K2b: k_pq — p/q per n, P/Q per row (true S2max) ----------
__global__ __launch_bounds__(256) void k_pq() {
    const float M = key2f(g_s2max_bits);
    int idx = blockIdx.x * 256 + threadIdx.x;
    if (idx < N_COLS) {
        float d = g_s2[idx] - M;
        g_p[idx] = expf(d);
        g_q[idx] = expf(ALPHA * d);
    } else {
        int b = idx - N_COLS;
        float s1 = -g_t[b];
        float v = s1 + M;
        float mh = fmaxf(v, ALPHA * v);
        g_P[b] = expf(v - mh);
        g_Q[b] = expf(ALPHA * v - mh);
    }
}

// ---------------- K3: k_wgen — w -> tiled smem-image layout ----------------
// grid (2, 128): split = split0 + x, 32-row b-group (y). Thread: 4 n in one
// ktile. Tile [128 rows x 64B], chunk c placed at c ^ ((row>>1)&3).
__global__ __launch_bounds__(256) void k_wgen(const int* __restrict__ mask,
                                              int split0) {
    const int split = split0 + blockIdx.x;
    const int b0 = blockIdx.y * 32;
    const int tid = threadIdx.x;
    const int ktile = tid >> 3;              // 0..31
    const int nk = (tid & 7) * 4;            // 0..28, n within tile
    const int n0 = split * NCHUNK + ktile * KT + nk;
    const int c = nk >> 3;                   // 16B chunk 0..3
    const int inoff = (nk & 7) * 2;          // 0 or 8 bytes

    const float4 p4 = *(const float4*)&g_p[n0];
    const float4 q4 = *(const float4*)&g_q[n0];
    const float4 s4 = *(const float4*)&g_s2[n0];
    const int* mp = mask + (size_t)b0 * N_COLS + n0;

    char* tbase = g_wt +
        ((size_t)((b0 >> 7) * NSPLIT + split) * NT + ktile) * ATILE;

#pragma unroll 4
    for (int r = 0; r < 32; r++) {
        const int b = b0 + r, bl = b & 127;
        const float T = g_t[b], P = g_P[b], Q = g_Q[b];
        int4 m = *(const int4*)mp;
        float w0 = m.x ? ((s4.x >= T) ? P * p4.x : Q * q4.x) : 0.f;
        float w1 = m.y ? ((s4.y >= T) ? P * p4.y : Q * q4.y) : 0.f;
        float w2 = m.z ? ((s4.z >= T) ? P * p4.z : Q * q4.z) : 0.f;
        float w3 = m.w ? ((s4.w >= T) ? P * p4.w : Q * q4.w) : 0.f;
        __half2 h01 = __floats2half2_rn(w0, w1);
        __half2 h23 = __floats2half2_rn(w2, w3);
        uint32_t off = (uint32_t)bl * 64 + ((c ^ ((bl >> 1) & 3)) << 4) + inoff;
        *(uint2*)(tbase + off) = make_uint2(*(uint32_t*)&h01, *(uint32_t*)&h23);
        mp += N_COLS;
    }
}

// ---------------- K4: k_gemm — bulk-copy fp16 HMMA GEMM ----------------
// grid (32, 2): btile (x), split = split0 + y. CTA 256 thr, tile 128b x 128f,
// 32 K-tiles of 32 n; A/B tiles via cp.async.bulk into 3-slot mbarrier ring.
__global__ __launch_bounds__(256, 2) void k_gemm(int split0) {
    extern __shared__ __align__(16) char dsm[];
    const uint32_t sb = smem_u32(dsm);
    const uint32_t Wt0 = sb;                 // + k*ATILE, k<3
    const uint32_t Ht0 = sb + 3 * ATILE;     // + k*BTILE, k<3
    const uint32_t mb0 = sb + 6 * ATILE;     // 3 mbarriers

    const int tid = threadIdx.x, lane = tid & 31, wid = tid >> 5;
    const int qr = lane >> 2, qc = lane & 3;
    const int b0w = (wid >> 1) * 32, f0w = (wid & 1) * 64;
    const int gb0 = blockIdx.x * 128;
    const int split = split0 + blockIdx.y;

    const char* awsrc = g_wt +
        ((size_t)(blockIdx.x * NSPLIT + split) * NT) * ATILE;
    const char* bhsrc = (const char*)g_hb + (size_t)split * NCHUNK * 256;

    if (tid == 0) {
#pragma unroll
        for (int k = 0; k < 3; k++) MBAR_INIT(mb0 + k * 8, 1);
        asm volatile("fence.proxy.async.shared::cta;" ::: "memory");
    }
    __syncthreads();

    // prologue: tiles 0, 1
    if (tid == 0) {
#pragma unroll
        for (int k = 0; k < 2; k++) {
            MBAR_EXPECT(mb0 + k * 8, ATILE + BTILE);
            cp_bulk(Wt0 + k * ATILE, awsrc + (size_t)k * ATILE, ATILE, mb0 + k * 8);
            cp_bulk(Ht0 + k * BTILE, bhsrc + (size_t)k * BTILE, BTILE, mb0 + k * 8);
        }
    }

    // ldmatrix per-lane offsets (swizzled layouts)
    const uint32_t lrow = (lane & 7) + ((lane >> 3) & 1) * 8;
    const uint32_t kh = (lane >> 4) & 1;          // 16B k-half select
    const uint32_t axor = ((b0w + lrow) >> 1) & 3;
    const uint32_t arow64 = (b0w + lrow) * 64;
    const uint32_t bxor = lrow & 7;
    const uint32_t fbase = (uint32_t)f0w >> 3;    // chunk base 0 or 8

    float d[2][8][4];
#pragma unroll
    for (int mb = 0; mb < 2; mb++)
#pragma unroll
        for (int fb = 0; fb < 8; fb++)
#pragma unroll
            for (int c = 0; c < 4; c++) d[mb][fb][c] = 0.f;

    for (int t = 0; t < NT; t++) {
        const int slot = t % 3;
        MBAR_WAIT(mb0 + slot * 8, (t / 3) & 1);
        __syncthreads();  // all see tile t; MMA(t-1) complete everywhere

        // issue tile t+2 into slot (t+2)%3 (freed by MMA(t-1))
        if (tid == 0 && t + 2 < NT) {
            const int k = (t + 2) % 3;
            MBAR_EXPECT(mb0 + k * 8, ATILE + BTILE);
            cp_bulk(Wt0 + k * ATILE, awsrc + (size_t)(t + 2) * ATILE, ATILE,
                    mb0 + k * 8);
            cp_bulk(Ht0 + k * BTILE, bhsrc + (size_t)(t + 2) * BTILE, BTILE,
                    mb0 + k * 8);
        }

        // MMA(t)
        const uint32_t Wb = Wt0 + slot * ATILE;
        const uint32_t Hb = Ht0 + slot * BTILE;
#pragma unroll
        for (int j = 0; j < 2; j++) {
            uint32_t a0[4], a1[4];
            uint32_t ac = ((2 * j + kh) ^ axor) << 4;
            ldsm4(a0, Wb + arow64 + ac);
            ldsm4(a1, Wb + arow64 + 1024 + ac);   // +16 rows * 64B
#pragma unroll
            for (int P = 0; P < 4; P++) {
                uint32_t b4[4];
                uint32_t cc = (fbase + 2 * P + kh) ^ bxor;
                ldsm4t(b4, Hb + (lrow + j * 16) * 256 + (cc << 4));
                mma_f16(d[0][2 * P], a0, b4[0], b4[1]);
                mma_f16(d[1][2 * P], a1, b4[0], b4[1]);
                mma_f16(d[0][2 * P + 1], a0, b4[2], b4[3]);
                mma_f16(d[1][2 * P + 1], a1, b4[2], b4[3]);
            }
        }
    }

    // epilogue: write partials (validated mapping)
    float* pbase = g_part + (size_t)split * B_ROWS * OUT_DIM;
#pragma unroll
    for (int mb = 0; mb < 2; mb++) {
        int br = gb0 + b0w + mb * 16 + qr;
#pragma unroll
        for (int fb = 0; fb < 8; fb++) {
            int f = f0w + fb * 8 + qc * 2;
            float* p0 = pbase + (size_t)br * OUT_DIM + f;
            *(float2*)p0 = make_float2(d[mb][fb][0], d[mb][fb][1]);
            *(float2*)(p0 + 8 * OUT_DIM) = make_float2(d[mb][fb][2], d[mb][fb][3]);
        }
    }
}

// ---------------- K5: reduce partials + L2 normalize ----------------
__global__ __launch_bounds__(128) void k_finish(float* __restrict__ out) {
    __shared__ float red[4];
    int b = blockIdx.x, f = threadIdx.x;
    float s = 0.f;
#pragma unroll
    for (int k = 0; k < NSPLIT; k++)
        s += g_part[((size_t)k * B_ROWS + b) * OUT_DIM + f];
    float ss = s * s;
#pragma unroll
    for (int o = 16; o; o >>= 1) ss += __shfl_xor_sync(0xffffffffu, ss, o);
    if ((f & 31) == 0) red[f >> 5] = ss;
    __syncthreads();
    float tot = red[0] + red[1] + red[2] + red[3];
    out[b * OUT_DIM + f] = s / fmaxf(sqrtf(tot), 1e-12f);
}

// ---------------- launch (multi-stream phased overlap) ----------------
extern "C" void kernel_launch(void* const* d_in, const int* in_sizes, int n_in,
                              void* d_out, int out_size) {
    const float* gf    = (const float*)d_in[0];  // [100000, 256]
    const int*   nodes = (const int*)d_in[1];    // [4096]
    const int*   un    = (const int*)d_in[2];    // [8192]
    const int*   mask  = (const int*)d_in[3];    // [4096, 8192]
    const float* W     = (const float*)d_in[4];  // [256, 128]
    const float* a1    = (const float*)d_in[5];  // [128]
    const float* a2    = (const float*)d_in[6];  // [128]
    float* out = (float*)d_out;                  // [4096, 128]

    static cudaStream_t sA = nullptr;
    static cudaEvent_t evRoot, evPrep, evPq, evW[4];
    static int inited = 0;
    const int SMEM = 6 * ATILE + 64;  // 3xA + 3xB + mbarriers = 49216
    if (!inited) {
        cudaFuncSetAttribute(k_gemm, cudaFuncAttributeMaxDynamicSharedMemorySize, SMEM);
        cudaStreamCreateWithFlags(&sA, cudaStreamNonBlocking);
        cudaEventCreateWithFlags(&evRoot, cudaEventDisableTiming);
        cudaEventCreateWithFlags(&evPrep, cudaEventDisableTiming);
        cudaEventCreateWithFlags(&evPq, cudaEventDisableTiming);
        for (int p = 0; p < 4; p++)
            cudaEventCreateWithFlags(&evW[p], cudaEventDisableTiming);
        inited = 1;
    }

    // fork side stream off the capture-origin stream
    cudaEventRecord(evRoot, 0);
    cudaStreamWaitEvent(sA, evRoot, 0);

    // prep (side) || hneigh (main); pq joins both
    k_prep<<<B_ROWS / 32, 256, 0, sA>>>(gf, nodes, W, a1);
    cudaEventRecord(evPrep, sA);
    k_hneigh<<<N_COLS / 32, 256>>>(gf, un, W, a2);
    cudaStreamWaitEvent(0, evPrep, 0);
    k_pq<<<(N_COLS + B_ROWS) / 256, 256>>>();
    cudaEventRecord(evPq, 0);
    cudaStreamWaitEvent(sA, evPq, 0);

    // phased pipeline: wgen(p) on side stream || gemm(p-1) on main stream
    for (int p = 0; p < 4; p++) {
        k_wgen<<<dim3(2, B_ROWS / 32), 256, 0, sA>>>(mask, 2 * p);
        cudaEventRecord(evW[p], sA);
        cudaStreamWaitEvent(0, evW[p], 0);
        k_gemm<<<dim3(B_ROWS / 128, 2), 256, SMEM>>>(2 * p);
    }

    k_finish<<<B_ROWS, 128>>>(out);
}

// round 17
// speedup vs baseline: 1.4250x; 1.4250x over previous
#include <cuda_runtime.h>
#include <cuda_fp16.h>
#include <cstdint>

#define IN_DIM  256
#define OUT_DIM 128
#define B_ROWS  4096
#define N_COLS  8192
#define ALPHA   0.2f
#define NSPLIT  8
#define NCHUNK  (N_COLS / NSPLIT)  // 1024 n per split
#define KT      32                 // n per K-tile
#define NT      (NCHUNK / KT)      // 32 tiles
#define ATILE   8192               // A tile bytes: 128 rows x 64B
#define BTILE   8192               // B tile bytes: 32 rows x 256B
#define HB_BLKS (N_COLS / 32)      // 256 h-producer blocks

// ---------------- device scratch (static, allocation-free) ----------------
__device__ __align__(16) __half g_hb[N_COLS * OUT_DIM];          // 2 MB, swizzled
// w tiles: [btile 32][split 8][ktile 32][8192 B] = 64 MB, smem-image layout
__device__ __align__(16) char g_wt[(size_t)32 * NSPLIT * NT * ATILE];
__device__ float g_s2[N_COLS];
__device__ float g_t[B_ROWS];   // -s1[b]
// static-init; replays recompute the same max (atomicMax idempotent at max)
__device__ unsigned int g_s2max_bits = 0u;
__device__ __align__(16) float g_part[(size_t)NSPLIT * B_ROWS * OUT_DIM]; // 16 MB

// ---------------- helpers ----------------
__device__ __forceinline__ uint32_t smem_u32(const void* p) {
    uint32_t a;
    asm("{ .reg .u64 t; cvta.to.shared.u64 t, %1; cvt.u32.u64 %0, t; }"
        : "=r"(a) : "l"(p));
    return a;
}
__device__ __forceinline__ void cpa16(uint32_t s, const void* g) {
    asm volatile("cp.async.cg.shared.global [%0], [%1], 16;" :: "r"(s), "l"(g));
}
__device__ __forceinline__ void cp_bulk(uint32_t dst, const void* src,
                                        uint32_t bytes, uint32_t mbar) {
    asm volatile(
        "cp.async.bulk.shared::cta.global.mbarrier::complete_tx::bytes "
        "[%0], [%1], %2, [%3];"
        :: "r"(dst), "l"(src), "r"(bytes), "r"(mbar) : "memory");
}
__device__ __forceinline__ void ldsm4(uint32_t* r, uint32_t a) {
    asm volatile("ldmatrix.sync.aligned.m8n8.x4.shared.b16 {%0,%1,%2,%3}, [%4];"
                 : "=r"(r[0]), "=r"(r[1]), "=r"(r[2]), "=r"(r[3]) : "r"(a));
}
__device__ __forceinline__ void ldsm4t(uint32_t* r, uint32_t a) {
    asm volatile("ldmatrix.sync.aligned.m8n8.x4.trans.shared.b16 {%0,%1,%2,%3}, [%4];"
                 : "=r"(r[0]), "=r"(r[1]), "=r"(r[2]), "=r"(r[3]) : "r"(a));
}
__device__ __forceinline__ void mma_f16(float* d, const uint32_t* a,
                                        uint32_t b0, uint32_t b1) {
    asm volatile(
        "mma.sync.aligned.m16n8k16.row.col.f32.f16.f16.f32 "
        "{%0,%1,%2,%3},{%4,%5,%6,%7},{%8,%9},{%0,%1,%2,%3};"
        : "+f"(d[0]), "+f"(d[1]), "+f"(d[2]), "+f"(d[3])
        : "r"(a[0]), "r"(a[1]), "r"(a[2]), "r"(a[3]), "r"(b0), "r"(b1));
}
#define MBAR_INIT(mb, c) \
    asm volatile("mbarrier.init.shared.b64 [%0], %1;" :: "r"((uint32_t)(mb)), "r"((uint32_t)(c)) : "memory")
#define MBAR_EXPECT(mb, bytes) \
    asm volatile("mbarrier.arrive.expect_tx.shared.b64 _, [%0], %1;" \
                 :: "r"((uint32_t)(mb)), "r"((uint32_t)(bytes)) : "memory")
#define MBAR_WAIT(mb, ph) do {                                                   \
    uint32_t _m = (uint32_t)(mb), _p = (uint32_t)(ph), _d;                       \
    asm volatile("{\n\t.reg .pred p;\n\t"                                        \
        "mbarrier.try_wait.parity.acquire.cta.shared::cta.b64 p, [%1], %2;\n\t"  \
        "selp.b32 %0, 1, 0, p;\n\t}" : "=r"(_d) : "r"(_m), "r"(_p) : "memory");  \
    if (!_d) {                                                                   \
        asm volatile("{\n\t.reg .pred P1;\n\t"                                   \
            "WL_%=:\n\t"                                                         \
            "mbarrier.try_wait.parity.acquire.cta.shared::cta.b64 P1, [%0], %1, 0x989680;\n\t" \
            "@P1 bra.uni WD_%=;\n\t"                                             \
            "bra.uni WL_%=;\n\t"                                                 \
            "WD_%=:\n\t}" :: "r"(_m), "r"(_p) : "memory");                       \
    }                                                                            \
} while (0)
__device__ __forceinline__ unsigned int f2key(float f) {
    int i = __float_as_int(f);
    return (i >= 0) ? ((unsigned)i ^ 0x80000000u) : ~(unsigned)i;
}
__device__ __forceinline__ float key2f(unsigned int k) {
    int i = (k & 0x80000000u) ? (int)(k ^ 0x80000000u) : (int)~k;
    return __int_as_float(i);
}

// ---------------- K1: k_hneigh — h = gf[un]@W, s2, max; +prep blocks -------
// blocks [0, 256): pipelined h producer (h stored swizzled: row r, 16B chunk
// c at c ^ (r & 7)). blocks [256, 384): prep path (Wa1 local, s1 -> g_t).
__global__ __launch_bounds__(256) void k_hneigh(
    const float* __restrict__ gf, const int* __restrict__ un,
    const float* __restrict__ W, const float* __restrict__ a2,
    const int* __restrict__ nodes, const float* __restrict__ a1) {
    __shared__ __align__(16) float As[2][32][36];
    __shared__ __align__(16) float Ws[2][32][132];
    __shared__ float sWa1[IN_DIM];
    int t = threadIdx.x, lane = t & 31, wid = t >> 5;

    if (blockIdx.x >= HB_BLKS) {
        // ---- prep path ----
        int pb = blockIdx.x - HB_BLKS;
        {
            const float* row = W + t * OUT_DIM;
            float s = 0.f;
#pragma unroll 8
            for (int c = 0; c < OUT_DIM; c++) s += row[c] * a1[c];
            sWa1[t] = s;
        }
        __syncthreads();
#pragma unroll
        for (int rr = 0; rr < 4; rr++) {
            int b = pb * 32 + wid * 4 + rr;
            const float* row = gf + (size_t)nodes[b] * IN_DIM;
            float s = 0.f;
#pragma unroll
            for (int k = lane; k < IN_DIM; k += 32) s += row[k] * sWa1[k];
#pragma unroll
            for (int o = 16; o; o >>= 1) s += __shfl_xor_sync(0xffffffffu, s, o);
            if (lane == 0) g_t[b] = -s;
        }
        return;
    }

    // ---- h producer path ----
    int r0 = blockIdx.x * 32;
    const int arow = t >> 3, ach = t & 7;
    const float* asrc = gf + (size_t)un[r0 + arow] * IN_DIM + ach * 4;
    uint32_t adst[2] = {smem_u32(&As[0][arow][ach * 4]),
                        smem_u32(&As[1][arow][ach * 4])};
    uint32_t wdst[2][4];
    const float* wsrc[4];
#pragma unroll
    for (int u = 0; u < 4; u++) {
        int idx = t * 4 + u, wrow = idx >> 5, wch = idx & 31;
        wsrc[u] = W + (size_t)wrow * OUT_DIM + wch * 4;
        wdst[0][u] = smem_u32(&Ws[0][wrow][wch * 4]);
        wdst[1][u] = smem_u32(&Ws[1][wrow][wch * 4]);
    }

    cpa16(adst[0], asrc);
#pragma unroll
    for (int u = 0; u < 4; u++) cpa16(wdst[0][u], wsrc[u]);
    asm volatile("cp.async.commit_group;");

    float acc[4][4] = {};
    for (int kb = 0; kb < 8; kb++) {
        const int cur = kb & 1;
        if (kb + 1 < 8) {
            cpa16(adst[cur ^ 1], asrc + (kb + 1) * 32);
#pragma unroll
            for (int u = 0; u < 4; u++)
                cpa16(wdst[cur ^ 1][u], wsrc[u] + (size_t)(kb + 1) * 32 * OUT_DIM);
            asm volatile("cp.async.commit_group;");
            asm volatile("cp.async.wait_group 1;");
        } else {
            asm volatile("cp.async.wait_group 0;");
        }
        __syncthreads();
#pragma unroll
        for (int kk = 0; kk < 32; kk++) {
            float4 wv = *(const float4*)&Ws[cur][kk][4 * lane];
            float wvv[4] = {wv.x, wv.y, wv.z, wv.w};
            float av[4];
#pragma unroll
            for (int i = 0; i < 4; i++) av[i] = As[cur][wid + 8 * i][kk];
#pragma unroll
            for (int i = 0; i < 4; i++)
#pragma unroll
                for (int c = 0; c < 4; c++) acc[i][c] += av[i] * wvv[c];
        }
        __syncthreads();
    }

    float4 a2v = *(const float4*)&a2[4 * lane];
    float wmax = -1e30f;
    char* hb = (char*)g_hb;
#pragma unroll
    for (int i = 0; i < 4; i++) {
        int r = r0 + wid + 8 * i;
        float part = acc[i][0] * a2v.x + acc[i][1] * a2v.y +
                     acc[i][2] * a2v.z + acc[i][3] * a2v.w;
#pragma unroll
        for (int o = 16; o; o >>= 1) part += __shfl_xor_sync(0xffffffffu, part, o);
        if (lane == 0) {
            g_s2[r] = part;
            wmax = fmaxf(wmax, part);
        }
        __half2 h01 = __floats2half2_rn(acc[i][0], acc[i][1]);
        __half2 h23 = __floats2half2_rn(acc[i][2], acc[i][3]);
        uint32_t off = (uint32_t)r * 256 + (((lane >> 1) ^ (r & 7)) << 4) +
                       (lane & 1) * 8;
        *(uint2*)(hb + off) = make_uint2(*(uint32_t*)&h01, *(uint32_t*)&h23);
    }
    if (lane == 0) atomicMax(&g_s2max_bits, f2key(wmax));
}

// ---------------- K2: k_wgen — w -> tiled smem-image layout ----------------
// grid (NSPLIT, 128): split (x), 32-row b-group (y). Thread: 4 n in one ktile.
// Tile [128 rows x 64B], chunk c placed at c ^ ((row>>1)&3).
// p/q per n and T/P/Q per row computed inline (k_pq folded in).
__global__ __launch_bounds__(256) void k_wgen(const int* __restrict__ mask) {
    __shared__ float sT[32], sP[32], sQ[32];
    const int split = blockIdx.x;
    const int b0 = blockIdx.y * 32;
    const int tid = threadIdx.x;
    const float M = key2f(g_s2max_bits);

    if (tid < 32) {
        int b = b0 + tid;
        float T = g_t[b];               // = -s1
        float v = -T + M;               // s1 + M
        float mh = fmaxf(v, ALPHA * v); // leaky(v) >= row max
        sT[tid] = T;
        sP[tid] = expf(v - mh);
        sQ[tid] = expf(ALPHA * v - mh);
    }

    const int ktile = tid >> 3;              // 0..31
    const int nk = (tid & 7) * 4;            // 0..28, n within tile
    const int n0 = split * NCHUNK + ktile * KT + nk;
    const int c = nk >> 3;                   // 16B chunk 0..3
    const int inoff = (nk & 7) * 2;          // 0 or 8 bytes

    const float4 s4 = *(const float4*)&g_s2[n0];
    const float4 p4 = make_float4(expf(s4.x - M), expf(s4.y - M),
                                  expf(s4.z - M), expf(s4.w - M));
    const float4 q4 = make_float4(expf(ALPHA * (s4.x - M)),
                                  expf(ALPHA * (s4.y - M)),
                                  expf(ALPHA * (s4.z - M)),
                                  expf(ALPHA * (s4.w - M)));
    const int* mp = mask + (size_t)b0 * N_COLS + n0;

    char* tbase = g_wt +
        ((size_t)((b0 >> 7) * NSPLIT + split) * NT + ktile) * ATILE;

    __syncthreads();

#pragma unroll 4
    for (int r = 0; r < 32; r++) {
        const int b = b0 + r, bl = b & 127;
        const float T = sT[r], P = sP[r], Q = sQ[r];
        int4 m = *(const int4*)mp;
        float w0 = m.x ? ((s4.x >= T) ? P * p4.x : Q * q4.x) : 0.f;
        float w1 = m.y ? ((s4.y >= T) ? P * p4.y : Q * q4.y) : 0.f;
        float w2 = m.z ? ((s4.z >= T) ? P * p4.z : Q * q4.z) : 0.f;
        float w3 = m.w ? ((s4.w >= T) ? P * p4.w : Q * q4.w) : 0.f;
        __half2 h01 = __floats2half2_rn(w0, w1);
        __half2 h23 = __floats2half2_rn(w2, w3);
        uint32_t off = (uint32_t)bl * 64 + ((c ^ ((bl >> 1) & 3)) << 4) + inoff;
        *(uint2*)(tbase + off) = make_uint2(*(uint32_t*)&h01, *(uint32_t*)&h23);
        mp += N_COLS;
    }
}

// ---------------- K3: k_gemm — bulk-copy fp16 HMMA GEMM ----------------
// grid (32, NSPLIT): btile (x), split (y). CTA 256 thr, tile 128b x 128f,
// 32 K-tiles of 32 n; A/B tiles via cp.async.bulk into 3-slot mbarrier ring.
__global__ __launch_bounds__(256, 2) void k_gemm() {
    extern __shared__ __align__(16) char dsm[];
    const uint32_t sb = smem_u32(dsm);
    const uint32_t Wt0 = sb;                 // + k*ATILE, k<3
    const uint32_t Ht0 = sb + 3 * ATILE;     // + k*BTILE, k<3
    const uint32_t mb0 = sb + 6 * ATILE;     // 3 mbarriers

    const int tid = threadIdx.x, lane = tid & 31, wid = tid >> 5;
    const int qr = lane >> 2, qc = lane & 3;
    const int b0w = (wid >> 1) * 32, f0w = (wid & 1) * 64;
    const int gb0 = blockIdx.x * 128;

    const char* awsrc = g_wt +
        ((size_t)(blockIdx.x * NSPLIT + blockIdx.y) * NT) * ATILE;
    const char* bhsrc = (const char*)g_hb + (size_t)blockIdx.y * NCHUNK * 256;

    if (tid == 0) {
#pragma unroll
        for (int k = 0; k < 3; k++) MBAR_INIT(mb0 + k * 8, 1);
        asm volatile("fence.proxy.async.shared::cta;" ::: "memory");
    }
    __syncthreads();

    // prologue: tiles 0, 1
    if (tid == 0) {
#pragma unroll
        for (int k = 0; k < 2; k++) {
            MBAR_EXPECT(mb0 + k * 8, ATILE + BTILE);
            cp_bulk(Wt0 + k * ATILE, awsrc + (size_t)k * ATILE, ATILE, mb0 + k * 8);
            cp_bulk(Ht0 + k * BTILE, bhsrc + (size_t)k * BTILE, BTILE, mb0 + k * 8);
        }
    }

    // ldmatrix per-lane offsets (swizzled layouts)
    const uint32_t lrow = (lane & 7) + ((lane >> 3) & 1) * 8;
    const uint32_t kh = (lane >> 4) & 1;          // 16B k-half select
    const uint32_t axor = ((b0w + lrow) >> 1) & 3;
    const uint32_t arow64 = (b0w + lrow) * 64;
    const uint32_t bxor = lrow & 7;
    const uint32_t fbase = (uint32_t)f0w >> 3;    // chunk base 0 or 8

    float d[2][8][4];
#pragma unroll
    for (int mb = 0; mb < 2; mb++)
#pragma unroll
        for (int fb = 0; fb < 8; fb++)
#pragma unroll
            for (int c = 0; c < 4; c++) d[mb][fb][c] = 0.f;

    for (int t = 0; t < NT; t++) {
        const int slot = t % 3;
        MBAR_WAIT(mb0 + slot * 8, (t / 3) & 1);
        __syncthreads();  // all see tile t; MMA(t-1) complete everywhere

        // issue tile t+2 into slot (t+2)%3 (freed by MMA(t-1))
        if (tid == 0 && t + 2 < NT) {
            const int k = (t + 2) % 3;
            MBAR_EXPECT(mb0 + k * 8, ATILE + BTILE);
            cp_bulk(Wt0 + k * ATILE, awsrc + (size_t)(t + 2) * ATILE, ATILE,
                    mb0 + k * 8);
            cp_bulk(Ht0 + k * BTILE, bhsrc + (size_t)(t + 2) * BTILE, BTILE,
                    mb0 + k * 8);
        }

        // MMA(t)
        const uint32_t Wb = Wt0 + slot * ATILE;
        const uint32_t Hb = Ht0 + slot * BTILE;
#pragma unroll
        for (int j = 0; j < 2; j++) {
            uint32_t a0[4], a1[4];
            uint32_t ac = ((2 * j + kh) ^ axor) << 4;
            ldsm4(a0, Wb + arow64 + ac);
            ldsm4(a1, Wb + arow64 + 1024 + ac);   // +16 rows * 64B
#pragma unroll
            for (int P = 0; P < 4; P++) {
                uint32_t b4[4];
                uint32_t cc = (fbase + 2 * P + kh) ^ bxor;
                ldsm4t(b4, Hb + (lrow + j * 16) * 256 + (cc << 4));
                mma_f16(d[0][2 * P], a0, b4[0], b4[1]);
                mma_f16(d[1][2 * P], a1, b4[0], b4[1]);
                mma_f16(d[0][2 * P + 1], a0, b4[2], b4[3]);
                mma_f16(d[1][2 * P + 1], a1, b4[2], b4[3]);
            }
        }
    }

    // epilogue: write partials (validated mapping)
    float* pbase = g_part + (size_t)blockIdx.y * B_ROWS * OUT_DIM;
#pragma unroll
    for (int mb = 0; mb < 2; mb++) {
        int br = gb0 + b0w + mb * 16 + qr;
#pragma unroll
        for (int fb = 0; fb < 8; fb++) {
            int f = f0w + fb * 8 + qc * 2;
            float* p0 = pbase + (size_t)br * OUT_DIM + f;
            *(float2*)p0 = make_float2(d[mb][fb][0], d[mb][fb][1]);
            *(float2*)(p0 + 8 * OUT_DIM) = make_float2(d[mb][fb][2], d[mb][fb][3]);
        }
    }
}

// ---------------- K4: reduce partials + L2 normalize ----------------
__global__ __launch_bounds__(128) void k_finish(float* __restrict__ out) {
    __shared__ float red[4];
    int b = blockIdx.x, f = threadIdx.x;
    float s = 0.f;
#pragma unroll
    for (int k = 0; k < NSPLIT; k++)
        s += g_part[((size_t)k * B_ROWS + b) * OUT_DIM + f];
    float ss = s * s;
#pragma unroll
    for (int o = 16; o; o >>= 1) ss += __shfl_xor_sync(0xffffffffu, ss, o);
    if ((f & 31) == 0) red[f >> 5] = ss;
    __syncthreads();
    float tot = red[0] + red[1] + red[2] + red[3];
    out[b * OUT_DIM + f] = s / fmaxf(sqrtf(tot), 1e-12f);
}

// ---------------- launch (serial, 4 kernels) ----------------
extern "C" void kernel_launch(void* const* d_in, const int* in_sizes, int n_in,
                              void* d_out, int out_size) {
    const float* gf    = (const float*)d_in[0];  // [100000, 256]
    const int*   nodes = (const int*)d_in[1];    // [4096]
    const int*   un    = (const int*)d_in[2];    // [8192]
    const int*   mask  = (const int*)d_in[3];    // [4096, 8192]
    const float* W     = (const float*)d_in[4];  // [256, 128]
    const float* a1    = (const float*)d_in[5];  // [128]
    const float* a2    = (const float*)d_in[6];  // [128]
    float* out = (float*)d_out;                  // [4096, 128]

    static int smem_set = 0;
    const int SMEM = 6 * ATILE + 64;  // 3xA + 3xB + mbarriers = 49216
    if (!smem_set) {
        cudaFuncSetAttribute(k_gemm, cudaFuncAttributeMaxDynamicSharedMemorySize, SMEM);
        smem_set = 1;
    }

    k_hneigh<<<HB_BLKS + B_ROWS / 32, 256>>>(gf, un, W, a2, nodes, a1);
    k_wgen<<<dim3(NSPLIT, B_ROWS / 32), 256>>>(mask);
    k_gemm<<<dim3(B_ROWS / 128, NSPLIT), 256, SMEM>>>();
    k_finish<<<B_ROWS, 128>>>(out);
}